// round 1
// baseline (speedup 1.0000x reference)
#include <cuda_runtime.h>
#include <cstdint>

// Problem constants
#define BB 8
#define TT 128
#define EE 256
#define HH 256
#define DD 512
#define CL 16
#define NTHREADS 256

// Output layout (float32, concatenated): outputs[8,128,256], seq_lengths[8],
// hidden[1,8,256], attn[8,128,128]
#define OUT_OFF     0
#define SEQ_OFF     262144
#define HID_OFF     262152
#define ATTN_OFF    264200

// Device scratch for precomputed x @ W1[:, :E]^T + b1  -> [B*T, D]
__device__ float g_xw1[1024 * 512];

// ---------------- SMEM layout (floats) ----------------
#define OFF_W1H   0        // [32][256]  W1[:,E:] rows for my k-chunk      8192
#define OFF_XW1   8192     // [8][512]   xW1 rows for my j-chunk           4096
#define OFF_WIHT  12288    // [16][1024] Wih columns for my e-chunk       16384
#define OFF_WHH   28672    // [64][256]  Whh rows for my gate rows        16384
#define OFF_X     45056    // [8][256]   x rows for my j-chunk             2048
#define OFF_W2    47104    // [512]
#define OFF_H     47616    // [256]  replicated h
#define OFF_HPROJ 47872    // [512]  replicated h@W1h^T
#define OFF_SUM   48384    // [16]   exp partial sums from each peer
#define OFF_CTXP  48400    // [16][16] context partials (from peer p, my 16 e's)
#define OFF_GATEP 48656    // [16][64] gate partials (from peer p, my 64 rows)
#define OFF_HWHH  49680    // [64]
#define OFF_BIAS  49744    // [64]
#define OFF_MYEXP 49808    // [8]
#define OFF_CTX16 49816    // [16]
#define OFF_C     49832    // [16]  cell state chunk
#define OFF_HPST  49848    // [32]  hproj chunk staging
#define OFF_GFIN  49880    // [64]  activated gates
#define OFF_HST   49944    // [16]  h_new chunk staging
#define OFF_MISC  49960    // [8]
#define SMEM_FLOATS 49968
#define SMEM_BYTES (SMEM_FLOATS * 4)

// ---------------- helpers ----------------
__device__ __forceinline__ unsigned crank() {
    unsigned r; asm("mov.u32 %0, %%cluster_ctarank;" : "=r"(r)); return r;
}

__device__ __forceinline__ float wsum(float v) {
    #pragma unroll
    for (int o = 16; o > 0; o >>= 1) v += __shfl_xor_sync(0xffffffffu, v, o);
    return v;
}

// store a float into peer CTA's shared memory (same smem offset)
__device__ __forceinline__ void stc(float* smem_ptr, int peer, float v) {
    uint32_t a = (uint32_t)__cvta_generic_to_shared(smem_ptr);
    uint32_t rp;
    asm volatile("mapa.shared::cluster.u32 %0, %1, %2;" : "=r"(rp) : "r"(a), "r"(peer));
    asm volatile("st.shared::cluster.f32 [%0], %1;" :: "r"(rp), "f"(v));
}

#define CLUSTER_SYNC() do { \
    asm volatile("barrier.cluster.arrive.aligned;" ::: "memory"); \
    asm volatile("barrier.cluster.wait.aligned;"   ::: "memory"); \
} while (0)

__device__ __forceinline__ float sigmoidf_(float x) { return 1.f / (1.f + expf(-x)); }

// ---------------- precompute GEMM: g_xw1[m][n] = b1[n] + sum_k x[m][k]*W1[n][k] ----------------
// M=1024 (b*T), N=512 (k-out), K=256 (e).  Both operands K-contiguous (NT).
__global__ void xw1_gemm(const float* __restrict__ X, const float* __restrict__ W1,
                         const float* __restrict__ b1) {
    __shared__ float As[64][33];
    __shared__ float Bs[64][33];
    const int m0 = blockIdx.x * 64, n0 = blockIdx.y * 64;
    const int tx = threadIdx.x, ty = threadIdx.y;
    const int tid = ty * 16 + tx;
    float acc[4][4] = {};
    for (int kt = 0; kt < 256; kt += 32) {
        for (int idx = tid; idx < 64 * 32; idx += 256) {
            int rr = idx >> 5, kk = idx & 31;
            As[rr][kk] = X[(m0 + rr) * 256 + kt + kk];
            Bs[rr][kk] = W1[(size_t)(n0 + rr) * 512 + kt + kk];
        }
        __syncthreads();
        #pragma unroll
        for (int kk = 0; kk < 32; kk++) {
            float a[4], bv[4];
            #pragma unroll
            for (int i = 0; i < 4; i++) { a[i] = As[ty*4+i][kk]; bv[i] = Bs[tx*4+i][kk]; }
            #pragma unroll
            for (int i = 0; i < 4; i++)
                #pragma unroll
                for (int j = 0; j < 4; j++) acc[i][j] += a[i] * bv[j];
        }
        __syncthreads();
    }
    #pragma unroll
    for (int i = 0; i < 4; i++) {
        #pragma unroll
        for (int j = 0; j < 4; j++) {
            int n = n0 + tx*4 + j;
            g_xw1[(size_t)(m0 + ty*4 + i) * 512 + n] = acc[i][j] + b1[n];
        }
    }
}

// ---------------- persistent recurrence kernel: 8 clusters (one per b) x 16 CTAs ----------------
__global__ void lstm_attn(const float* __restrict__ x, const int* __restrict__ seqlen,
                          const float* __restrict__ W1, const float* __restrict__ W2,
                          const float* __restrict__ b2w, const float* __restrict__ Wih,
                          const float* __restrict__ Whh, const float* __restrict__ bih,
                          const float* __restrict__ bhh, float* __restrict__ out) {
    extern __shared__ float sm[];
    const int tid = threadIdx.x;
    const int w = tid >> 5, lane = tid & 31;
    const int r = (int)crank();
    const int b = blockIdx.x >> 4;
    const int len = seqlen[b];
    const float b2v = b2w[0];

    // ---- prologue: load all per-CTA weight slices into SMEM ----
    for (int idx = tid; idx < 32 * 256; idx += NTHREADS) {          // W1h rows [32r..32r+32)
        int i = idx >> 8, d = idx & 255;
        sm[OFF_W1H + idx] = W1[(size_t)(32 * r + i) * 512 + 256 + d];
    }
    for (int idx = tid; idx < 8 * 512; idx += NTHREADS)             // xW1 rows j in [8r..8r+8)
        sm[OFF_XW1 + idx] = g_xw1[(size_t)(b * 128 + 8 * r) * 512 + idx];
    for (int idx = tid; idx < 16 * 1024; idx += NTHREADS) {         // Wih^T cols e in [16r..16r+16)
        int e = idx >> 10, g = idx & 1023;
        sm[OFF_WIHT + idx] = Wih[(size_t)g * 256 + 16 * r + e];
    }
    for (int idx = tid; idx < 64 * 256; idx += NTHREADS) {          // Whh rows for my gate rows
        int q = idx >> 8, d = idx & 255;
        int gate = q >> 4, i = q & 15;
        sm[OFF_WHH + idx] = Whh[(size_t)(gate * 256 + 16 * r + i) * 256 + d];
    }
    for (int idx = tid; idx < 8 * 256; idx += NTHREADS)             // x rows j in [8r..8r+8)
        sm[OFF_X + idx] = x[(size_t)(b * 128 + 8 * r) * 256 + idx];
    for (int idx = tid; idx < 512; idx += NTHREADS) sm[OFF_W2 + idx] = W2[idx];
    if (tid < 64) {
        int gate = tid >> 4, i = tid & 15;
        int row = gate * 256 + 16 * r + i;
        sm[OFF_BIAS + tid] = bih[row] + bhh[row];
    }
    for (int idx = tid; idx < 256; idx += NTHREADS) sm[OFF_H + idx] = 0.f;
    if (tid < 16) sm[OFF_C + tid] = 0.f;
    if (r == 0 && tid == 0) out[SEQ_OFF + b] = (float)len;
    __syncthreads();
    CLUSTER_SYNC();   // syncA(0): everyone's buffers initialized, h replicated (zeros)

    for (int t = 0; t < TT; t++) {
        const bool active = t < len;

        // ---- P1: hproj chunk (warps 0-3) + h@Whh rows (warps 4-7), using replicated h ----
        if (w < 4) {
            #pragma unroll
            for (int rr = 0; rr < 8; rr++) {
                int kl = w * 8 + rr;
                float acc = 0.f;
                #pragma unroll
                for (int ii = 0; ii < 8; ii++) {
                    int d = lane + 32 * ii;
                    acc += sm[OFF_W1H + kl * 256 + d] * sm[OFF_H + d];
                }
                acc = wsum(acc);
                if (lane == 0) sm[OFF_HPST + kl] = acc;
            }
        } else {
            #pragma unroll
            for (int rr = 0; rr < 16; rr++) {
                int q = (w - 4) * 16 + rr;
                float acc = 0.f;
                #pragma unroll
                for (int ii = 0; ii < 8; ii++) {
                    int d = lane + 32 * ii;
                    acc += sm[OFF_WHH + q * 256 + d] * sm[OFF_H + d];
                }
                acc = wsum(acc);
                if (lane == 0) sm[OFF_HWHH + q] = acc;
            }
        }
        __syncthreads();
        // all-gather hproj chunk to every peer (incl. self)
        for (int idx = tid; idx < 32 * CL; idx += NTHREADS) {
            int kl = idx >> 4, peer = idx & 15;
            stc(&sm[OFF_HPROJ + 32 * r + kl], peer, sm[OFF_HPST + kl]);
        }
        CLUSTER_SYNC();  // syncB: full hproj everywhere

        // ---- P3: energies for my 8 j's (one warp per j), exp + partial sum ----
        {
            const int j = w;
            float acc = 0.f;
            #pragma unroll
            for (int ii = 0; ii < 16; ii++) {
                int k = lane + 32 * ii;
                acc += tanhf(sm[OFF_XW1 + j * 512 + k] + sm[OFF_HPROJ + k]) * sm[OFF_W2 + k];
            }
            acc = wsum(acc);
            if (lane == 0) {
                float e = tanhf(acc + b2v);
                bool vj = (8 * r + j) < len;
                // energies are tanh outputs in [-1,1] -> no max-subtraction needed
                sm[OFF_MYEXP + j] = vj ? expf(e) : 0.f;
            }
        }
        __syncthreads();
        if (tid == 0) {
            float ps = 0.f;
            #pragma unroll
            for (int j = 0; j < 8; j++) ps += sm[OFF_MYEXP + j];
            sm[OFF_MISC] = ps;
        }
        __syncthreads();
        if (tid < CL) stc(&sm[OFF_SUM + r], tid, sm[OFF_MISC]);
        CLUSTER_SYNC();  // syncC: all 16 exp partial sums everywhere

        // ---- P4: softmax weights (my j's), attn output, context partials ----
        float S = 0.f;
        #pragma unroll
        for (int p = 0; p < CL; p++) S += sm[OFF_SUM + p];
        const float Sinv = 1.f / S;
        if (tid < 8) {
            float wv = active ? sm[OFF_MYEXP + tid] * Sinv : 0.f;
            sm[OFF_MYEXP + tid] = wv;                       // now holds w_j
            out[ATTN_OFF + (size_t)(b * 128 + t) * 128 + 8 * r + tid] = wv;
        }
        __syncthreads();
        {
            const int e = tid;  // 256 threads = 256 embedding dims
            float cp = 0.f;
            #pragma unroll
            for (int j = 0; j < 8; j++) cp += sm[OFF_MYEXP + j] * sm[OFF_X + j * 256 + e];
            int peer = e >> 4;
            stc(&sm[OFF_CTXP + r * 16 + (e & 15)], peer, cp);
        }
        CLUSTER_SYNC();  // syncD: context partials delivered (reduce-scatter)

        // ---- P5: finalize my 16 context dims; gate partials for all 1024 gates ----
        if (tid < 16) {
            float s = 0.f;
            #pragma unroll
            for (int p = 0; p < CL; p++) s += sm[OFF_CTXP + p * 16 + tid];
            sm[OFF_CTX16 + tid] = s;
        }
        __syncthreads();
        {
            float a0 = 0.f, a1 = 0.f, a2 = 0.f, a3 = 0.f;
            const float4* wT = (const float4*)&sm[OFF_WIHT];
            #pragma unroll
            for (int e = 0; e < 16; e++) {
                float cv = sm[OFF_CTX16 + e];
                float4 v = wT[e * 256 + tid];
                a0 += cv * v.x; a1 += cv * v.y; a2 += cv * v.z; a3 += cv * v.w;
            }
            float av[4] = {a0, a1, a2, a3};
            #pragma unroll
            for (int i2 = 0; i2 < 4; i2++) {
                int g = tid * 4 + i2;
                int peer = (g & 255) >> 4;
                int q = (g >> 8) * 16 + (g & 15);
                stc(&sm[OFF_GATEP + r * 64 + q], peer, av[i2]);
            }
        }
        CLUSTER_SYNC();  // syncE: gate partials delivered (reduce-scatter)

        // ---- P6: finalize gates, LSTM update, write outputs, broadcast h chunk ----
        if (tid < 64) {
            float g = 0.f;
            #pragma unroll
            for (int p = 0; p < CL; p++) g += sm[OFF_GATEP + p * 64 + tid];
            g += sm[OFF_HWHH + tid] + sm[OFF_BIAS + tid];
            int gate = tid >> 4;
            sm[OFF_GFIN + tid] = (gate == 2) ? tanhf(g) : sigmoidf_(g);
        }
        __syncthreads();
        if (tid < 16) {
            float c = sm[OFF_GFIN + 16 + tid] * sm[OFF_C + tid]
                    + sm[OFF_GFIN + tid] * sm[OFF_GFIN + 32 + tid];
            sm[OFF_C + tid] = c;
            float hn = sm[OFF_GFIN + 48 + tid] * tanhf(c);
            out[(size_t)(b * 128 + t) * 256 + 16 * r + tid] = active ? hn : 0.f;
            if (t == len - 1) out[HID_OFF + b * 256 + 16 * r + tid] = hn;
            sm[OFF_HST + tid] = hn;
        }
        __syncthreads();
        for (int idx = tid; idx < 16 * CL; idx += NTHREADS) {
            int i = idx & 15, peer = idx >> 4;
            stc(&sm[OFF_H + 16 * r + i], peer, sm[OFF_HST + i]);
        }
        CLUSTER_SYNC();  // syncA: h replicated for next step
    }
}

// ---------------- host launch ----------------
extern "C" void kernel_launch(void* const* d_in, const int* in_sizes, int n_in,
                              void* d_out, int out_size) {
    const float* x   = (const float*)d_in[0];
    const int*   sl  = (const int*)  d_in[1];
    const float* W1  = (const float*)d_in[2];
    const float* b1  = (const float*)d_in[3];
    const float* W2  = (const float*)d_in[4];
    const float* b2  = (const float*)d_in[5];
    const float* Wih = (const float*)d_in[6];
    const float* Whh = (const float*)d_in[7];
    const float* bih = (const float*)d_in[8];
    const float* bhh = (const float*)d_in[9];
    float* out = (float*)d_out;

    // 1) precompute xW1 = x @ W1[:, :E]^T + b1
    xw1_gemm<<<dim3(16, 8), dim3(16, 16)>>>(x, W1, b1);

    // 2) persistent clustered recurrence kernel
    cudaFuncSetAttribute(lstm_attn, cudaFuncAttributeNonPortableClusterSizeAllowed, 1);
    cudaFuncSetAttribute(lstm_attn, cudaFuncAttributeMaxDynamicSharedMemorySize, SMEM_BYTES);

    cudaLaunchConfig_t cfg = {};
    cfg.gridDim = dim3(BB * CL, 1, 1);
    cfg.blockDim = dim3(NTHREADS, 1, 1);
    cfg.dynamicSmemBytes = SMEM_BYTES;
    cfg.stream = 0;
    cudaLaunchAttribute attrs[1];
    attrs[0].id = cudaLaunchAttributeClusterDimension;
    attrs[0].val.clusterDim.x = CL;
    attrs[0].val.clusterDim.y = 1;
    attrs[0].val.clusterDim.z = 1;
    cfg.attrs = attrs;
    cfg.numAttrs = 1;

    cudaLaunchKernelEx(&cfg, lstm_attn, x, sl, W1, W2, b2, Wih, Whh, bih, bhh, out);
}

// round 2
// speedup vs baseline: 1.3304x; 1.3304x over previous
#include <cuda_runtime.h>
#include <cstdint>

// Problem constants
#define BB 8
#define TT 128
#define CL 16
#define NTHREADS 256

// Output layout (float32, concatenated): outputs[8,128,256], seq_lengths[8],
// hidden[1,8,256], attn[8,128,128]
#define SEQ_OFF     262144
#define HID_OFF     262152
#define ATTN_OFF    264200

// Device scratch for precomputed x @ W1[:, :E]^T + b1  -> [B*T, D]
__device__ float g_xw1[1024 * 512];

// ---------------- SMEM layout (float offsets) ----------------
#define OFF_W1H   0        // [32][256]   W1 h-cols, my 32 k rows
#define OFF_WHH   8192     // [64][256]   Whh rows for my 64 gate rows
#define OFF_WIHT  24576    // [16][1024]  Wih^T for my 16 e's
#define OFF_XW1   40960    // [128][33]   xw1[j][my 32 k] (pitch 33)
#define OFF_X     45184    // [128][17]   x[j][my 16 e]   (pitch 17)
#define OFF_W2    47360    // [32]        W2[my 32 k]
#define OFF_HBUF  47392    // [2][256]    replicated h (double buffered)
#define OFF_EP    47904    // [2][16][128] energy partials from each peer
#define OFF_GP    52000    // [2][16][64]  gate partials from each peer
#define OFF_HPST  54048    // [32]  my hproj slice
#define OFF_HWST  54080    // [64]  my h@Whh rows
#define OFF_BIAS  54144    // [64]
#define OFF_PST   54208    // [128] my energy partials (staging)
#define OFF_WB    54336    // [128] softmax weights (all j, local)
#define OFF_CTX   54464    // [16]  my context dims
#define OFF_GFIN  54480    // [64]  activated gates
#define OFF_CST   54544    // [16]  cell state
#define OFF_HST   54560    // [16]  h_new chunk staging
#define OFF_SRED  54576    // [8]   softmax-sum warp partials
#define OFF_MBAR  54584    // 6 mbarriers x 8B (h0,h1,ep0,ep1,gp0,gp1)
#define SMEM_FLOATS 54608
#define SMEM_BYTES (SMEM_FLOATS * 4)

// ---------------- helpers ----------------
__device__ __forceinline__ unsigned crank() {
    unsigned r; asm("mov.u32 %0, %%cluster_ctarank;" : "=r"(r)); return r;
}
__device__ __forceinline__ uint32_t smem_u32(const void* p) {
    uint32_t a;
    asm("{ .reg .u64 t; cvta.to.shared.u64 t, %1; cvt.u32.u64 %0, t; }" : "=r"(a) : "l"(p));
    return a;
}
__device__ __forceinline__ uint32_t mapa_(uint32_t a, int peer) {
    uint32_t r;
    asm("mapa.shared::cluster.u32 %0, %1, %2;" : "=r"(r) : "r"(a), "r"(peer));
    return r;
}
// remote smem store of 8 bytes + tx-signal on remote mbarrier
__device__ __forceinline__ void st_async2(uint32_t raddr, uint32_t rmbar, float vx, float vy) {
    unsigned long long p;
    asm("mov.b64 %0, {%1,%2};" : "=l"(p) : "f"(vx), "f"(vy));
    asm volatile("st.async.shared::cluster.mbarrier::complete_tx::bytes.b64 [%0], %1, [%2];"
                 :: "r"(raddr), "l"(p), "r"(rmbar) : "memory");
}
__device__ __forceinline__ void mbar_init(uint32_t mb, uint32_t cnt) {
    asm volatile("mbarrier.init.shared.b64 [%0], %1;" :: "r"(mb), "r"(cnt) : "memory");
}
__device__ __forceinline__ void mbar_arm(uint32_t mb, uint32_t tx) {
    asm volatile("mbarrier.arrive.expect_tx.shared.b64 _, [%0], %1;" :: "r"(mb), "r"(tx) : "memory");
}
__device__ __forceinline__ void mwait(uint32_t mb, uint32_t ph) {
    uint32_t done = 0;
    do {
        asm volatile("{\n\t.reg .pred p;\n\t"
                     "mbarrier.try_wait.parity.acquire.cta.shared::cta.b64 p, [%1], %2, 0x989680;\n\t"
                     "selp.b32 %0, 1, 0, p;\n\t}"
                     : "=r"(done) : "r"(mb), "r"(ph) : "memory");
    } while (!done);
}
__device__ __forceinline__ float wsum(float v) {
    #pragma unroll
    for (int o = 16; o > 0; o >>= 1) v += __shfl_xor_sync(0xffffffffu, v, o);
    return v;
}
#define CLUSTER_SYNC() do { \
    asm volatile("barrier.cluster.arrive.aligned;" ::: "memory"); \
    asm volatile("barrier.cluster.wait.aligned;"   ::: "memory"); \
} while (0)

// ---------------- precompute GEMM: g_xw1[m][n] = b1[n] + sum_k x[m][k]*W1[n][k] ----------------
__global__ void xw1_gemm(const float* __restrict__ X, const float* __restrict__ W1,
                         const float* __restrict__ b1) {
    __shared__ float As[64][33];
    __shared__ float Bs[64][33];
    const int m0 = blockIdx.x * 64, n0 = blockIdx.y * 64;
    const int tx = threadIdx.x, ty = threadIdx.y;
    const int tid = ty * 16 + tx;
    float acc[4][4] = {};
    for (int kt = 0; kt < 256; kt += 32) {
        for (int idx = tid; idx < 64 * 32; idx += 256) {
            int rr = idx >> 5, kk = idx & 31;
            As[rr][kk] = X[(m0 + rr) * 256 + kt + kk];
            Bs[rr][kk] = W1[(size_t)(n0 + rr) * 512 + kt + kk];
        }
        __syncthreads();
        #pragma unroll
        for (int kk = 0; kk < 32; kk++) {
            float a[4], bv[4];
            #pragma unroll
            for (int i = 0; i < 4; i++) { a[i] = As[ty*4+i][kk]; bv[i] = Bs[tx*4+i][kk]; }
            #pragma unroll
            for (int i = 0; i < 4; i++)
                #pragma unroll
                for (int j = 0; j < 4; j++) acc[i][j] += a[i] * bv[j];
        }
        __syncthreads();
    }
    #pragma unroll
    for (int i = 0; i < 4; i++)
        #pragma unroll
        for (int j = 0; j < 4; j++) {
            int n = n0 + tx*4 + j;
            g_xw1[(size_t)(m0 + ty*4 + i) * 512 + n] = acc[i][j] + b1[n];
        }
}

// ---------------- persistent recurrence: 8 clusters (1/batch) x 16 CTAs, mbarrier p2p sync ----------------
__global__ void __launch_bounds__(NTHREADS, 1)
lstm_attn(const float* __restrict__ x, const int* __restrict__ seqlen,
          const float* __restrict__ W1, const float* __restrict__ W2,
          const float* __restrict__ b2w, const float* __restrict__ Wih,
          const float* __restrict__ Whh, const float* __restrict__ bih,
          const float* __restrict__ bhh, float* __restrict__ out) {
    extern __shared__ float sm[];
    const int tid = threadIdx.x;
    const int w = tid >> 5, lane = tid & 31;
    const int r = (int)crank();
    const int b = blockIdx.x >> 4;
    const int len = seqlen[b];
    const float b2v = b2w[0];
    const uint32_t smb = smem_u32(sm);
    const uint32_t MB = smb + 4u * OFF_MBAR;   // mbar i at MB + 8*i

    // ---- prologue: weight slices ----
    for (int idx = tid; idx < 32 * 256; idx += NTHREADS) {          // W1 h-cols, k rows [32r,32r+32)
        int row = idx >> 8, d = idx & 255;
        sm[OFF_W1H + idx] = W1[(size_t)(32 * r + row) * 512 + 256 + d];
    }
    for (int idx = tid; idx < 64 * 256; idx += NTHREADS) {          // Whh rows for my gates
        int q = idx >> 8, d = idx & 255;
        int gate = q >> 4, i = q & 15;
        sm[OFF_WHH + idx] = Whh[(size_t)(gate * 256 + 16 * r + i) * 256 + d];
    }
    for (int idx = tid; idx < 16 * 1024; idx += NTHREADS) {         // Wih^T for e in [16r,16r+16)
        int e = idx >> 10, g = idx & 1023;
        sm[OFF_WIHT + idx] = Wih[(size_t)g * 256 + 16 * r + e];
    }
    for (int idx = tid; idx < 128 * 32; idx += NTHREADS) {          // xw1[j][32r+kk], pitch 33
        int j = idx >> 5, kk = idx & 31;
        sm[OFF_XW1 + j * 33 + kk] = g_xw1[(size_t)(b * 128 + j) * 512 + 32 * r + kk];
    }
    for (int idx = tid; idx < 128 * 16; idx += NTHREADS) {          // x[j][16r+e], pitch 17
        int j = idx >> 4, e = idx & 15;
        sm[OFF_X + j * 17 + e] = x[(size_t)(b * 128 + j) * 256 + 16 * r + e];
    }
    if (tid < 32) sm[OFF_W2 + tid] = W2[32 * r + tid];
    if (tid < 64) {
        int gate = tid >> 4, i = tid & 15;
        int row = gate * 256 + 16 * r + i;
        sm[OFF_BIAS + tid] = bih[row] + bhh[row];
    }
    if (tid < 16) { sm[OFF_CST + tid] = 0.f; sm[OFF_HST + tid] = 0.f; }
    if (r == 0 && tid == 0) out[SEQ_OFF + b] = (float)len;

    if (tid == 0) {
        #pragma unroll
        for (int i = 0; i < 6; i++) mbar_init(MB + 8u * i, 1);
        asm volatile("fence.mbarrier_init.release.cluster;" ::: "memory");
        mbar_arm(MB + 8u * 0, 1024);   // h[0]
        mbar_arm(MB + 8u * 2, 8192);   // ep[0]
        mbar_arm(MB + 8u * 4, 4096);   // gp[0]
    }
    __syncthreads();
    CLUSTER_SYNC();   // mbarrier inits visible cluster-wide before any st.async

    // seed h(0)=0 into everyone's hbuf[0] (completes mbar h[0])
    if (tid < 128) {
        int peer = tid >> 3, pr = tid & 7;
        uint32_t dst = smb + 4u * (OFF_HBUF + 16 * r + 2 * pr);
        st_async2(mapa_(dst, peer), mapa_(MB + 8u * 0, peer), 0.f, 0.f);
    }

    for (int t = 0; t < TT; t++) {
        const int  buf = t & 1;
        const uint32_t ph = (t >> 1) & 1;
        const bool active = t < len;
        const uint32_t mb_h  = MB + 8u * (buf);
        const uint32_t mb_ep = MB + 8u * (2 + buf);
        const uint32_t mb_gp = MB + 8u * (4 + buf);

        // arm next-step barriers (their previous phase completed at step t-1)
        if (tid == 0) {
            int nb = (t + 1) & 1;
            mbar_arm(MB + 8u * (nb),     1024);
            mbar_arm(MB + 8u * (2 + nb), 8192);
            mbar_arm(MB + 8u * (4 + nb), 4096);
        }

        // ---- wait replicated h, compute hproj slice (32) + h@Whh rows (64) ----
        mwait(mb_h, ph);
        {
            const float* hb = sm + OFF_HBUF + buf * 256;
            float4 h0 = *(const float4*)(hb + lane * 8);
            float4 h1 = *(const float4*)(hb + lane * 8 + 4);
            #pragma unroll
            for (int rr = 0; rr < 12; rr++) {
                int row = w * 12 + rr;
                const float* wr = (row < 32) ? (sm + OFF_W1H + row * 256)
                                             : (sm + OFF_WHH + (row - 32) * 256);
                float4 a0 = *(const float4*)(wr + lane * 8);
                float4 a1 = *(const float4*)(wr + lane * 8 + 4);
                float acc = a0.x*h0.x + a0.y*h0.y + a0.z*h0.z + a0.w*h0.w
                          + a1.x*h1.x + a1.y*h1.y + a1.z*h1.z + a1.w*h1.w;
                acc = wsum(acc);
                if (lane == 0) {
                    if (row < 32) sm[OFF_HPST + row] = acc;
                    else          sm[OFF_HWST + row - 32] = acc;
                }
            }
        }
        __syncthreads();

        // ---- energy partials over my 32 k's, ALL 128 j's ----
        {
            int j = tid >> 1, half = tid & 1;
            const float* xw = sm + OFF_XW1 + j * 33 + half * 16;
            const float* hp = sm + OFF_HPST + half * 16;
            const float* w2 = sm + OFF_W2 + half * 16;
            float acc = 0.f;
            #pragma unroll
            for (int i = 0; i < 16; i++) acc += tanhf(xw[i] + hp[i]) * w2[i];
            acc += __shfl_xor_sync(0xffffffffu, acc, 1);
            if (!half) sm[OFF_PST + j] = acc;
        }
        __syncthreads();
        // all-gather my 128 partials to every peer's epbuf[buf][r][*]
        {
            int peer = tid >> 4, c8 = (tid & 15) * 8;
            uint32_t dst = smb + 4u * (OFF_EP + buf * 2048 + r * 128 + c8);
            uint32_t rdst = mapa_(dst, peer), rmb = mapa_(mb_ep, peer);
            const float2* src = (const float2*)(sm + OFF_PST + c8);
            #pragma unroll
            for (int m = 0; m < 4; m++) st_async2(rdst + 8u * m, rmb, src[m].x, src[m].y);
        }

        // ---- wait partials; full softmax locally ----
        mwait(mb_ep, ph);
        float ex = 0.f;
        if (tid < 128) {
            const float* epb = sm + OFF_EP + buf * 2048;
            float s = b2v;
            #pragma unroll
            for (int p = 0; p < 16; p++) s += epb[p * 128 + tid];
            float e = tanhf(s);                       // energy in [-1,1]: no max-sub needed
            ex = (tid < len) ? expf(e) : 0.f;
        }
        float wp = wsum(ex);
        if (lane == 0) sm[OFF_SRED + w] = wp;
        __syncthreads();
        {
            float S = sm[OFF_SRED] + sm[OFF_SRED+1] + sm[OFF_SRED+2] + sm[OFF_SRED+3];
            float Sinv = 1.f / S;
            if (tid < 128) {
                float wv = active ? ex * Sinv : 0.f;
                sm[OFF_WB + tid] = wv;
                if ((tid >> 3) == r)
                    out[ATTN_OFF + (size_t)(b * 128 + t) * 128 + tid] = wv;
            }
        }
        __syncthreads();

        // ---- context dims [16r,16r+16) from ALL j ----
        {
            int e = 2 * w + (lane >> 4);
            int jb = (lane & 15) * 8;
            const float* xc = sm + OFF_X + jb * 17 + e;
            const float* wb = sm + OFF_WB + jb;
            float cp = 0.f;
            #pragma unroll
            for (int jj = 0; jj < 8; jj++) cp += wb[jj] * xc[jj * 17];
            #pragma unroll
            for (int o = 8; o > 0; o >>= 1) cp += __shfl_xor_sync(0xffffffffu, cp, o);
            if ((lane & 15) == 0) sm[OFF_CTX + e] = cp;
        }
        __syncthreads();

        // ---- gate partials for all 1024 gate rows; reduce-scatter to owners ----
        {
            const float4* wT = (const float4*)(sm + OFF_WIHT);
            float a0 = 0.f, a1 = 0.f, a2 = 0.f, a3 = 0.f;
            #pragma unroll
            for (int e2 = 0; e2 < 16; e2++) {
                float cv = sm[OFF_CTX + e2];
                float4 v = wT[e2 * 256 + tid];
                a0 += cv * v.x; a1 += cv * v.y; a2 += cv * v.z; a3 += cv * v.w;
            }
            int g0 = tid * 4;
            int owner = (g0 & 255) >> 4;
            int q0 = ((g0 >> 8) << 4) + (g0 & 15);
            uint32_t dst = smb + 4u * (OFF_GP + buf * 1024 + r * 64 + q0);
            uint32_t rdst = mapa_(dst, owner), rmb = mapa_(mb_gp, owner);
            st_async2(rdst,      rmb, a0, a1);
            st_async2(rdst + 8u, rmb, a2, a3);
        }

        // ---- wait gate partials; LSTM update for my 16 h dims ----
        mwait(mb_gp, ph);
        if (tid < 64) {
            const float* gpb = sm + OFF_GP + buf * 1024;
            float g = sm[OFF_HWST + tid] + sm[OFF_BIAS + tid];
            #pragma unroll
            for (int p = 0; p < 16; p++) g += gpb[p * 64 + tid];
            sm[OFF_GFIN + tid] = ((tid >> 4) == 2) ? tanhf(g) : 1.f / (1.f + expf(-g));
        }
        __syncthreads();
        if (tid < 16) {
            float c = sm[OFF_GFIN + 16 + tid] * sm[OFF_CST + tid]
                    + sm[OFF_GFIN + tid] * sm[OFF_GFIN + 32 + tid];
            sm[OFF_CST + tid] = c;
            float hn = sm[OFF_GFIN + 48 + tid] * tanhf(c);
            out[(size_t)(b * 128 + t) * 256 + 16 * r + tid] = active ? hn : 0.f;
            if (t == len - 1) out[HID_OFF + b * 256 + 16 * r + tid] = hn;
            sm[OFF_HST + tid] = hn;
        }
        __syncthreads();

        // ---- broadcast my h chunk for step t+1 (skip last: no in-flight DSMEM at exit) ----
        if (t < TT - 1 && tid < 128) {
            int peer = tid >> 3, pr = tid & 7;
            uint32_t dst = smb + 4u * (OFF_HBUF + ((t + 1) & 1) * 256 + 16 * r + 2 * pr);
            const float2 v = *(const float2*)(sm + OFF_HST + 2 * pr);
            st_async2(mapa_(dst, peer), mapa_(MB + 8u * ((t + 1) & 1), peer), v.x, v.y);
        }
    }
}

// ---------------- host launch ----------------
extern "C" void kernel_launch(void* const* d_in, const int* in_sizes, int n_in,
                              void* d_out, int out_size) {
    const float* x   = (const float*)d_in[0];
    const int*   sl  = (const int*)  d_in[1];
    const float* W1  = (const float*)d_in[2];
    const float* b1  = (const float*)d_in[3];
    const float* W2  = (const float*)d_in[4];
    const float* b2  = (const float*)d_in[5];
    const float* Wih = (const float*)d_in[6];
    const float* Whh = (const float*)d_in[7];
    const float* bih = (const float*)d_in[8];
    const float* bhh = (const float*)d_in[9];
    float* out = (float*)d_out;

    xw1_gemm<<<dim3(16, 8), dim3(16, 16)>>>(x, W1, b1);

    cudaFuncSetAttribute(lstm_attn, cudaFuncAttributeNonPortableClusterSizeAllowed, 1);
    cudaFuncSetAttribute(lstm_attn, cudaFuncAttributeMaxDynamicSharedMemorySize, SMEM_BYTES);

    cudaLaunchConfig_t cfg = {};
    cfg.gridDim = dim3(BB * CL, 1, 1);
    cfg.blockDim = dim3(NTHREADS, 1, 1);
    cfg.dynamicSmemBytes = SMEM_BYTES;
    cfg.stream = 0;
    cudaLaunchAttribute attrs[1];
    attrs[0].id = cudaLaunchAttributeClusterDimension;
    attrs[0].val.clusterDim.x = CL;
    attrs[0].val.clusterDim.y = 1;
    attrs[0].val.clusterDim.z = 1;
    cfg.attrs = attrs;
    cfg.numAttrs = 1;

    cudaLaunchKernelEx(&cfg, lstm_attn, x, sl, W1, W2, b2, Wih, Whh, bih, bhh, out);
}